// round 5
// baseline (speedup 1.0000x reference)
#include <cuda_runtime.h>
#include <math.h>

#define FULLMASK 0xffffffffu
#define LSZ 64
#define HSZ 32
#define BATCH 1024
#define WPB  4          // warps per block
#define EPW  2          // batch elements per warp
#define ELEM_FLOATS (2 * LSZ * HSZ)      // double-buffered carry grid per element

// ---- packed f32x2 helpers (sm_103a) ----
__device__ __forceinline__ float2 ffma2(float2 a, float2 b, float2 c) {
    unsigned long long ua = reinterpret_cast<unsigned long long&>(a);
    unsigned long long ub = reinterpret_cast<unsigned long long&>(b);
    unsigned long long uc = reinterpret_cast<unsigned long long&>(c);
    asm("fma.rn.f32x2 %0, %1, %2, %0;" : "+l"(uc) : "l"(ua), "l"(ub));
    return reinterpret_cast<float2&>(uc);
}
__device__ __forceinline__ float2 fadd2(float2 a, float2 b) {
    unsigned long long ua = reinterpret_cast<unsigned long long&>(a);
    unsigned long long ub = reinterpret_cast<unsigned long long&>(b);
    unsigned long long ud;
    asm("add.rn.f32x2 %0, %1, %2;" : "=l"(ud) : "l"(ua), "l"(ub));
    return reinterpret_cast<float2&>(ud);
}

extern __shared__ float sdyn[];   // [WPB*EPW][2][LSZ][HSZ]

__global__ __launch_bounds__(WPB * 32, 1)
void rnn2d_kernel(const int*   __restrict__ x,     // [B,64,64]
                  const float* __restrict__ Win,   // [4,32]
                  const float* __restrict__ WcH,   // [32,32]
                  const float* __restrict__ WcV,   // [32,32]
                  const float* __restrict__ bV,    // [32]
                  const float* __restrict__ Wout,  // [32,2]
                  const float* __restrict__ bout,  // [2]
                  float*       __restrict__ out)   // [B]
{
    __shared__ float s_wod[HSZ];

    const int lane = threadIdx.x & 31;
    const int w    = threadIdx.x >> 5;
    const int b0   = (blockIdx.x * WPB + w) * EPW;   // first element of this warp

    // per-element carry grids (scan/logical order, double buffered)
    float* S0 = sdyn + (size_t)(w * EPW + 0) * ELEM_FLOATS;
    float* S1 = sdyn + (size_t)(w * EPW + 1) * ELEM_FLOATS;

    // ---- weights -> registers (shared by both elements) ----
    float2 WH[16], WV[16];
#pragma unroll
    for (int m = 0; m < 16; ++m) {
        WH[m] = make_float2(WcH[(2 * m) * HSZ + lane], WcH[(2 * m + 1) * HSZ + lane]);
        WV[m] = make_float2(WcV[(2 * m) * HSZ + lane], WcV[(2 * m + 1) * HSZ + lane]);
    }
    const float W0 = Win[lane], W1 = Win[HSZ + lane];
    const float W2 = Win[2 * HSZ + lane], W3 = Win[3 * HSZ + lane];
    const float bVl = bV[lane];
    if (threadIdx.x < HSZ)
        s_wod[threadIdx.x] = Wout[threadIdx.x * 2 + 0] - Wout[threadIdx.x * 2 + 1];
    const float bd = bout[0] - bout[1];

    // zero initial read buffers (row 0 reads buffer 0 = zeros)
#pragma unroll
    for (int c = 0; c < LSZ; ++c) {
        S0[c * HSZ + lane] = 0.f;
        S1[c * HSZ + lane] = 0.f;
    }
    __syncthreads();   // s_wod ready (carries are warp-local)

    const int* xA = x + (size_t)(b0 + 0) * (LSZ * LSZ);
    const int* xB = x + (size_t)(b0 + 1) * (LSZ * LSZ);
    int cA0 = xA[lane], cA1 = xA[HSZ + lane];
    int cB0 = xB[lane], cB1 = xB[HSZ + lane];
    unsigned long long prevA = 0ull, prevB = 0ull;
    float sumA = 0.f, sumB = 0.f;

#pragma unroll 1
    for (int r = 0; r < LSZ; ++r) {
        unsigned int a0b = __ballot_sync(FULLMASK, cA0);
        unsigned int a1b = __ballot_sync(FULLMASK, cA1);
        unsigned int b0b = __ballot_sync(FULLMASK, cB0);
        unsigned int b1b = __ballot_sync(FULLMASK, cB1);
        unsigned long long rawA = (unsigned long long)a0b | ((unsigned long long)a1b << 32);
        unsigned long long rawB = (unsigned long long)b0b | ((unsigned long long)b1b << 32);
        if (r < LSZ - 1) {
            cA0 = xA[(r + 1) * LSZ + lane]; cA1 = xA[(r + 1) * LSZ + HSZ + lane];
            cB0 = xB[(r + 1) * LSZ + lane]; cB1 = xB[(r + 1) * LSZ + HSZ + lane];
        }
        const bool fwd = ((r & 1) == 0);
        const unsigned long long cmA = fwd ? rawA : __brevll(rawA);
        const unsigned long long pmA = fwd ? prevA : __brevll(prevA);
        const unsigned long long cmB = fwd ? rawB : __brevll(rawB);
        const unsigned long long pmB = fwd ? prevB : __brevll(prevB);
        prevA = rawA; prevB = rawB;
        const float eW2 = r ? W2 : 0.f;
        const float eW3 = r ? W3 : 0.f;

        const int rb = r & 1, wb = rb ^ 1;
        const float4* rpA = reinterpret_cast<const float4*>(S0 + rb * (LSZ * HSZ) + (LSZ - 1) * HSZ);
        const float4* rpB = reinterpret_cast<const float4*>(S1 + rb * (LSZ * HSZ) + (LSZ - 1) * HSZ);
        const float4* hpA = reinterpret_cast<const float4*>(S0 + wb * (LSZ * HSZ));
        const float4* hpB = reinterpret_cast<const float4*>(S1 + wb * (LSZ * HSZ));
        float* wpA = S0 + wb * (LSZ * HSZ) + lane;
        float* wpB = S1 + wb * (LSZ * HSZ) + lane;

        // ---- j = 0 (no horizontal term) ----
        {
            __syncwarp();
            float baseA = bVl + ((pmA & 1ull) ? eW3 : eW2);
            float baseB = bVl + ((pmB & 1ull) ? eW3 : eW2);
            float2 aA0 = make_float2(0.f, 0.f), aA1 = aA0;
            float2 aB0 = aA0, aB1 = aA0;
#pragma unroll
            for (int m = 0; m < 8; ++m) {
                float4 fA = rpA[m];
                float4 fB = rpB[m];
                aA0 = ffma2(WV[2 * m],     make_float2(fA.x, fA.y), aA0);
                aA1 = ffma2(WV[2 * m + 1], make_float2(fA.z, fA.w), aA1);
                aB0 = ffma2(WV[2 * m],     make_float2(fB.x, fB.y), aB0);
                aB1 = ffma2(WV[2 * m + 1], make_float2(fB.z, fB.w), aB1);
            }
            float2 sA = fadd2(aA0, aA1);
            float2 sB = fadd2(aB0, aB1);
            float vA = baseA + sA.x + sA.y;
            float vB = baseB + sB.x + sB.y;
            float eA = __expf(vA) - 1.0f;
            float eB = __expf(vB) - 1.0f;
            wpA[0] = (vA > 0.f) ? vA : eA;
            wpB[0] = (vB > 0.f) ? vB : eB;
            rpA -= 8; rpB -= 8;
        }
        unsigned long long pmjA = pmA >> 1, cmjA = cmA;
        unsigned long long pmjB = pmB >> 1, cmjB = cmB;

        // ---- j = 1..63, both elements per iteration ----
#pragma unroll 1
        for (int j = 1; j < LSZ; ++j) {
            __syncwarp();
            float baseA = bVl + ((cmjA & 1ull) ? W1 : W0) + ((pmjA & 1ull) ? eW3 : eW2);
            float baseB = bVl + ((cmjB & 1ull) ? W1 : W0) + ((pmjB & 1ull) ? eW3 : eW2);
            cmjA >>= 1; pmjA >>= 1; cmjB >>= 1; pmjB >>= 1;
            float2 aA0 = make_float2(0.f, 0.f), aA1 = aA0, cA0v = aA0, cA1v = aA0;
            float2 aB0 = aA0, aB1 = aA0, cB0v = aA0, cB1v = aA0;
#pragma unroll
            for (int m = 0; m < 8; ++m) {
                float4 fA = rpA[m];   // vertical carry (prev row)
                float4 gA = hpA[m];   // h-vector (prev column)
                float4 fB = rpB[m];
                float4 gB = hpB[m];
                aA0  = ffma2(WV[2 * m],     make_float2(fA.x, fA.y), aA0);
                aA1  = ffma2(WV[2 * m + 1], make_float2(fA.z, fA.w), aA1);
                cA0v = ffma2(WH[2 * m],     make_float2(gA.x, gA.y), cA0v);
                cA1v = ffma2(WH[2 * m + 1], make_float2(gA.z, gA.w), cA1v);
                aB0  = ffma2(WV[2 * m],     make_float2(fB.x, fB.y), aB0);
                aB1  = ffma2(WV[2 * m + 1], make_float2(fB.z, fB.w), aB1);
                cB0v = ffma2(WH[2 * m],     make_float2(gB.x, gB.y), cB0v);
                cB1v = ffma2(WH[2 * m + 1], make_float2(gB.z, gB.w), cB1v);
            }
            float2 sA = fadd2(fadd2(aA0, aA1), fadd2(cA0v, cA1v));
            float2 sB = fadd2(fadd2(aB0, aB1), fadd2(cB0v, cB1v));
            float vA = baseA + sA.x + sA.y;
            float vB = baseB + sB.x + sB.y;
            float eA = __expf(vA) - 1.0f;
            float eB = __expf(vB) - 1.0f;
            wpA[j * HSZ] = (vA > 0.f) ? vA : eA;
            wpB[j * HSZ] = (vB > 0.f) ? vB : eB;
            rpA -= 8; hpA += 8; rpB -= 8; hpB += 8;
        }
        __syncwarp();

        // ---- epilogue: per-column 2-class log-softmax (lane owns cols lane, lane+32)
        const float* hbA = S0 + wb * (LSZ * HSZ);
        const float* hbB = S1 + wb * (LSZ * HSZ);
        const int l32 = lane * HSZ;
        float dA0 = 0.f, dA1 = 0.f, dB0 = 0.f, dB1 = 0.f;
#pragma unroll
        for (int m = 0; m < 32; ++m) {
            int   idx = lane ^ m;              // conflict-free rotation
            float wv  = s_wod[idx];
            dA0 = fmaf(hbA[l32 + idx],             wv, dA0);
            dA1 = fmaf(hbA[l32 + HSZ * HSZ + idx], wv, dA1);
            dB0 = fmaf(hbB[l32 + idx],             wv, dB0);
            dB1 = fmaf(hbB[l32 + HSZ * HSZ + idx], wv, dB1);
        }
        float uA0 = dA0 + bd, uA1 = dA1 + bd;
        float uB0 = dB0 + bd, uB1 = dB1 + bd;
        int sA0 = (int)((cmA >> lane) & 1ull);
        int sA1 = (int)((cmA >> (lane + 32)) & 1ull);
        int sB0 = (int)((cmB >> lane) & 1ull);
        int sB1 = (int)((cmB >> (lane + 32)) & 1ull);
        float tA0 = sA0 ? uA0 : -uA0;
        float tA1 = sA1 ? uA1 : -uA1;
        float tB0 = sB0 ? uB0 : -uB0;
        float tB1 = sB1 ? uB1 : -uB1;
        float lA0 = -fmaxf(tA0, 0.f) - log1pf(__expf(-fabsf(tA0)));
        float lA1 = -fmaxf(tA1, 0.f) - log1pf(__expf(-fabsf(tA1)));
        float lB0 = -fmaxf(tB0, 0.f) - log1pf(__expf(-fabsf(tB0)));
        float lB1 = -fmaxf(tB1, 0.f) - log1pf(__expf(-fabsf(tB1)));
        if (isnan(lA0)) lA0 = -35.f;
        if (isnan(lA1)) lA1 = -35.f;
        if (isnan(lB0)) lB0 = -35.f;
        if (isnan(lB1)) lB1 = -35.f;
        sumA += lA0 + lA1;
        sumB += lB0 + lB1;
    }

    float tA = sumA, tB = sumB;
#pragma unroll
    for (int off = 16; off; off >>= 1) {
        tA += __shfl_xor_sync(FULLMASK, tA, off);
        tB += __shfl_xor_sync(FULLMASK, tB, off);
    }
    if (lane == 0) {
        out[b0 + 0] = 0.5f * tA;
        out[b0 + 1] = 0.5f * tB;
    }
}

extern "C" void kernel_launch(void* const* d_in, const int* in_sizes, int n_in,
                              void* d_out, int out_size)
{
    const int*   x    = (const int*)  d_in[0];
    const float* Win  = (const float*)d_in[1];
    const float* WcH  = (const float*)d_in[2];
    const float* WcV  = (const float*)d_in[3];
    const float* bV   = (const float*)d_in[4];
    const float* Wout = (const float*)d_in[5];
    const float* bout = (const float*)d_in[6];

    const int smem = WPB * EPW * ELEM_FLOATS * sizeof(float);   // 131072 B
    // Not stream-ordered, idempotent, deterministic — safe under graph capture.
    cudaFuncSetAttribute(rnn2d_kernel,
                         cudaFuncAttributeMaxDynamicSharedMemorySize, smem);
    const int blocks = BATCH / (WPB * EPW);   // 128
    rnn2d_kernel<<<blocks, WPB * 32, smem>>>(x, Win, WcH, WcV, bV, Wout, bout,
                                             (float*)d_out);
}

// round 7
// speedup vs baseline: 1.1081x; 1.1081x over previous
#include <cuda_runtime.h>
#include <math.h>

#define FULLMASK 0xffffffffu
#define LSZ 64
#define HSZ 32
#define BATCH 1024

// ---- packed f32x2 helpers (sm_103a) ----
__device__ __forceinline__ float2 ffma2(float2 a, float2 b, float2 c) {
    unsigned long long ua = reinterpret_cast<unsigned long long&>(a);
    unsigned long long ub = reinterpret_cast<unsigned long long&>(b);
    unsigned long long uc = reinterpret_cast<unsigned long long&>(c);
    asm("fma.rn.f32x2 %0, %1, %2, %0;" : "+l"(uc) : "l"(ua), "l"(ub));
    return reinterpret_cast<float2&>(uc);
}
__device__ __forceinline__ float2 fadd2(float2 a, float2 b) {
    unsigned long long ua = reinterpret_cast<unsigned long long&>(a);
    unsigned long long ub = reinterpret_cast<unsigned long long&>(b);
    unsigned long long ud;
    asm("add.rn.f32x2 %0, %1, %2;" : "=l"(ud) : "l"(ua), "l"(ub));
    return reinterpret_cast<float2&>(ud);
}

__global__ __launch_bounds__(32)
void rnn2d_kernel(const int*   __restrict__ x,     // [B,64,64]
                  const float* __restrict__ Win,   // [4,32]
                  const float* __restrict__ WcH,   // [32,32]
                  const float* __restrict__ WcV,   // [32,32]
                  const float* __restrict__ bV,    // [32]
                  const float* __restrict__ Wout,  // [32,2]
                  const float* __restrict__ bout,  // [2]
                  float*       __restrict__ out)   // [B]
{
    // carries in SCAN (snake-logical) order, double-buffered by row
    __shared__ float s_c[2][LSZ][HSZ];   // 16 KB
    __shared__ float s_P[LSZ][HSZ];      //  8 KB  (chain-independent terms)
    __shared__ float s_wod[HSZ];

    const int lane = threadIdx.x;        // owns hidden index `lane`
    const int b    = blockIdx.x;

    // ---- weights -> registers ----
    float2 WH[16], WV[16];
#pragma unroll
    for (int m = 0; m < 16; ++m) {
        WH[m] = make_float2(WcH[(2 * m) * HSZ + lane], WcH[(2 * m + 1) * HSZ + lane]);
        WV[m] = make_float2(WcV[(2 * m) * HSZ + lane], WcV[(2 * m + 1) * HSZ + lane]);
    }
    const float W0 = Win[lane], W1 = Win[HSZ + lane];
    const float W2 = Win[2 * HSZ + lane], W3 = Win[3 * HSZ + lane];
    const float bVl = bV[lane];
    s_wod[lane] = Wout[lane * 2 + 0] - Wout[lane * 2 + 1];
    const float bd = bout[0] - bout[1];

#pragma unroll
    for (int c = 0; c < LSZ; ++c) s_c[0][c][lane] = 0.f;   // row 0 reads zeros

    const int* xb = x + (size_t)b * (LSZ * LSZ);
    int cur0 = xb[lane];
    int cur1 = xb[HSZ + lane];
    unsigned long long rawprev = 0ull;
    float lanesum = 0.f;
    __syncwarp();

#pragma unroll 1
    for (int r = 0; r < LSZ; ++r) {
        unsigned int b0 = __ballot_sync(FULLMASK, cur0);
        unsigned int b1 = __ballot_sync(FULLMASK, cur1);
        unsigned long long raw = (unsigned long long)b0 |
                                 ((unsigned long long)b1 << 32);
        if (r < LSZ - 1) {
            cur0 = xb[(r + 1) * LSZ + lane];
            cur1 = xb[(r + 1) * LSZ + HSZ + lane];
        }
        const bool fwd = ((r & 1) == 0);
        const unsigned long long cm = fwd ? raw : __brevll(raw);
        const unsigned long long pm = fwd ? rawprev : __brevll(rawprev);
        rawprev = raw;
        const float eW2 = r ? W2 : 0.f;
        const float eW3 = r ? W3 : 0.f;

        const int rb = r & 1, wb = rb ^ 1;

        // ================= PHASE 1: chain-free precompute of P[j] ==========
        // P[j][lane] = bV + WcV^T*carryV(scan j) + Win one-hot terms.
        // prev-row carry for scan j lives at logical slot 63-j (snake mirror).
        {
            const float4* rp = reinterpret_cast<const float4*>(&s_c[rb][LSZ - 1][0]);
            // ---- j = 0 (no horizontal one-hot) ----
            {
                float2 a0 = make_float2(bVl + ((pm & 1ull) ? eW3 : eW2), 0.f);
                float2 a1 = make_float2(0.f, 0.f);
#pragma unroll
                for (int m = 0; m < 8; ++m) {
                    float4 f = rp[m];
                    a0 = ffma2(WV[2 * m],     make_float2(f.x, f.y), a0);
                    a1 = ffma2(WV[2 * m + 1], make_float2(f.z, f.w), a1);
                }
                float2 s = fadd2(a0, a1);
                s_P[0][lane] = s.x + s.y;
                rp -= 8;
            }
            unsigned long long vm = pm >> 1;   // bit0 = vsel for j=1
            unsigned long long hm = cm;        // bit0 = hsel for j=1
#pragma unroll 4
            for (int j = 1; j < LSZ; ++j) {
                float base = bVl + ((hm & 1ull) ? W1 : W0)
                                 + ((vm & 1ull) ? eW3 : eW2);
                hm >>= 1; vm >>= 1;
                float2 a0 = make_float2(base, 0.f);
                float2 a1 = make_float2(0.f, 0.f);
#pragma unroll
                for (int m = 0; m < 8; ++m) {
                    float4 f = rp[m];
                    a0 = ffma2(WV[2 * m],     make_float2(f.x, f.y), a0);
                    a1 = ffma2(WV[2 * m + 1], make_float2(f.z, f.w), a1);
                }
                float2 s = fadd2(a0, a1);
                s_P[j][lane] = s.x + s.y;
                rp -= 8;
            }
        }
        // P is read only by the writing lane -> no sync needed.

        // ================= PHASE 2: latency-bound recurrence ================
        {
            // j = 0: h = elu(P[0])
            float v0 = s_P[0][lane];
            float e0 = __expf(v0) - 1.0f;
            s_c[wb][0][lane] = (v0 > 0.f) ? v0 : e0;

            const float4* hp = reinterpret_cast<const float4*>(&s_c[wb][0][0]);
#pragma unroll 7
            for (int j = 1; j < LSZ; ++j) {
                float Pj = s_P[j][lane];
                __syncwarp();                       // h-vector of step j-1 visible
                float4 g0 = hp[0], g1 = hp[1], g2 = hp[2], g3 = hp[3];
                float4 g4 = hp[4], g5 = hp[5], g6 = hp[6], g7 = hp[7];
                // 8 accumulators, FFMA2 depth 2 -> short chain
                float2 a0 = make_float2(Pj, 0.f);
                float2 a1 = make_float2(0.f, 0.f), a2 = a1, a3 = a1;
                float2 a4 = a1, a5 = a1, a6 = a1, a7 = a1;
                a0 = ffma2(WH[0],  make_float2(g0.x, g0.y), a0);
                a1 = ffma2(WH[1],  make_float2(g0.z, g0.w), a1);
                a2 = ffma2(WH[2],  make_float2(g1.x, g1.y), a2);
                a3 = ffma2(WH[3],  make_float2(g1.z, g1.w), a3);
                a4 = ffma2(WH[4],  make_float2(g2.x, g2.y), a4);
                a5 = ffma2(WH[5],  make_float2(g2.z, g2.w), a5);
                a6 = ffma2(WH[6],  make_float2(g3.x, g3.y), a6);
                a7 = ffma2(WH[7],  make_float2(g3.z, g3.w), a7);
                a0 = ffma2(WH[8],  make_float2(g4.x, g4.y), a0);
                a1 = ffma2(WH[9],  make_float2(g4.z, g4.w), a1);
                a2 = ffma2(WH[10], make_float2(g5.x, g5.y), a2);
                a3 = ffma2(WH[11], make_float2(g5.z, g5.w), a3);
                a4 = ffma2(WH[12], make_float2(g6.x, g6.y), a4);
                a5 = ffma2(WH[13], make_float2(g6.z, g6.w), a5);
                a6 = ffma2(WH[14], make_float2(g7.x, g7.y), a6);
                a7 = ffma2(WH[15], make_float2(g7.z, g7.w), a7);
                float2 s = fadd2(fadd2(fadd2(a0, a1), fadd2(a2, a3)),
                                 fadd2(fadd2(a4, a5), fadd2(a6, a7)));
                float v = s.x + s.y;
                float e = __expf(v) - 1.0f;
                s_c[wb][j][lane] = (v > 0.f) ? v : e;
                hp += 8;
            }
        }
        __syncwarp();                               // all h stored before epilogue

        // ================= PHASE 3: per-row output head =====================
        const float* hb = &s_c[wb][0][0];
        const int l32 = lane * HSZ;
        float d0 = 0.f, d1 = 0.f;                   // scan cols lane, lane+32
#pragma unroll
        for (int m = 0; m < 32; ++m) {
            int   idx = lane ^ m;                   // conflict-free rotation
            float wv  = s_wod[idx];
            d0 = fmaf(hb[l32 + idx],             wv, d0);
            d1 = fmaf(hb[l32 + HSZ * HSZ + idx], wv, d1);
        }
        float u0 = d0 + bd, u1 = d1 + bd;           // z0 - z1 per column
        int sp0 = (int)((cm >> lane) & 1ull);
        int sp1 = (int)((cm >> (lane + 32)) & 1ull);
        float t0 = sp0 ? u0 : -u0;
        float t1 = sp1 ? u1 : -u1;
        float lp0 = -fmaxf(t0, 0.f) - log1pf(__expf(-fabsf(t0)));
        float lp1 = -fmaxf(t1, 0.f) - log1pf(__expf(-fabsf(t1)));
        if (isnan(lp0)) lp0 = -35.f;
        if (isnan(lp1)) lp1 = -35.f;
        lanesum += lp0 + lp1;
        __syncwarp();                               // epilogue reads done before next row
    }

    float tot = lanesum;
#pragma unroll
    for (int off = 16; off; off >>= 1)
        tot += __shfl_xor_sync(FULLMASK, tot, off);
    if (lane == 0) out[b] = 0.5f * tot;
}

extern "C" void kernel_launch(void* const* d_in, const int* in_sizes, int n_in,
                              void* d_out, int out_size)
{
    const int*   x    = (const int*)  d_in[0];
    const float* Win  = (const float*)d_in[1];
    const float* WcH  = (const float*)d_in[2];
    const float* WcV  = (const float*)d_in[3];
    const float* bV   = (const float*)d_in[4];
    const float* Wout = (const float*)d_in[5];
    const float* bout = (const float*)d_in[6];

    rnn2d_kernel<<<BATCH, 32>>>(x, Win, WcH, WcV, bV, Wout, bout, (float*)d_out);
}